// round 4
// baseline (speedup 1.0000x reference)
#include <cuda_runtime.h>
#include <cstdint>
#include <cmath>

#define GH 512
#define GK 50
#define KPAD 52
#define GT 1024
#define GB 128
#define GM (GB * GT)
#define BPP 56
#define JP 56            // padded j count (states per step, padded)

// Scratch for projected features [B*T, K] (+64 pad so padded-j reads stay in bounds)
__device__ float g_feats[(size_t)GM * GK + 64];

// Packed fp32x2 FMA (sm_103a): acc = x * w + acc
#define FFMA2(acc, x, w) \
    asm("fma.rn.f32x2 %0, %1, %2, %0;" : "+l"(acc) : "l"(x), "l"(w))

// ---------------------------------------------------------------------------
// Kernel 1 (round-1 proven, 212us): feats = hidden @ W^T + b
// 256 CTAs x 256 threads, 2 rows/thread. W transposed in smem [h][52],
// broadcast LDS.128 conflict-free; all math packed f32x2 FFMA.
// ---------------------------------------------------------------------------
__global__ __launch_bounds__(256, 1) void gemm_kernel(
    const float* __restrict__ hidden, const float* __restrict__ W,
    const float* __restrict__ bias) {
    extern __shared__ float Wt[];  // [GH][KPAD]
    const int tid = threadIdx.x;

    for (int idx = tid; idx < GK * GH; idx += 256) {
        int k = idx >> 9;
        int h = idx & 511;
        Wt[h * KPAD + k] = W[idx];
    }
    __syncthreads();

    const size_t base = (size_t)blockIdx.x * 512;
    const float4* r0 = reinterpret_cast<const float4*>(hidden + (base + tid) * GH);
    const float4* r1 = reinterpret_cast<const float4*>(hidden + (base + tid + 256) * GH);

    unsigned long long acc0[25], acc1[25];
#pragma unroll
    for (int q = 0; q < 25; q++) { acc0[q] = 0ull; acc1[q] = 0ull; }

    float4 a0 = r0[0], a1 = r0[1];
    float4 b0 = r1[0], b1 = r1[1];

    for (int hc = 0; hc < 64; hc++) {
        float xs0[8] = {a0.x, a0.y, a0.z, a0.w, a1.x, a1.y, a1.z, a1.w};
        float xs1[8] = {b0.x, b0.y, b0.z, b0.w, b1.x, b1.y, b1.z, b1.w};
        if (hc < 63) {
            a0 = r0[2 * hc + 2]; a1 = r0[2 * hc + 3];
            b0 = r1[2 * hc + 2]; b1 = r1[2 * hc + 3];
        }
#pragma unroll
        for (int u = 0; u < 8; u++) {
            const int h = hc * 8 + u;
            unsigned long long X0, X1;
            asm("mov.b64 %0, {%1, %1};" : "=l"(X0) : "r"(__float_as_uint(xs0[u])));
            asm("mov.b64 %0, {%1, %1};" : "=l"(X1) : "r"(__float_as_uint(xs1[u])));
            const float* wr = Wt + h * KPAD;
#pragma unroll
            for (int q = 0; q < 12; q++) {
                ulonglong2 w = *reinterpret_cast<const ulonglong2*>(wr + q * 4);
                FFMA2(acc0[2 * q],     X0, w.x);
                FFMA2(acc0[2 * q + 1], X0, w.y);
                FFMA2(acc1[2 * q],     X1, w.x);
                FFMA2(acc1[2 * q + 1], X1, w.y);
            }
            unsigned long long wl = *reinterpret_cast<const unsigned long long*>(wr + 48);
            FFMA2(acc0[24], X0, wl);
            FFMA2(acc1[24], X1, wl);
        }
    }

    float2* o0 = reinterpret_cast<float2*>(g_feats + (base + tid) * GK);
    float2* o1 = reinterpret_cast<float2*>(g_feats + (base + tid + 256) * GK);
    const float2* bb = reinterpret_cast<const float2*>(bias);
#pragma unroll
    for (int q = 0; q < 25; q++) {
        float2 bv = bb[q];
        float2 v0 = *reinterpret_cast<float2*>(&acc0[q]);
        float2 v1 = *reinterpret_cast<float2*>(&acc1[q]);
        v0.x += bv.x; v0.y += bv.y;
        v1.x += bv.x; v1.y += bv.y;
        o0[q] = v0;
        o1[q] = v1;
    }
}

// ---------------------------------------------------------------------------
// Pairwise argmax tree (select-form). Adjacent pairs keep index-ordered
// subranges; strict '>' (right wins only if strictly greater) == first-max.
// ---------------------------------------------------------------------------
template <int W>
__device__ __forceinline__ void argmax_tree(float* val, int* id) {
    if constexpr (W > 1) {
        constexpr int P = W >> 1;
#pragma unroll
        for (int m = 0; m < P; m++) {
            bool g = val[2 * m + 1] > val[2 * m];
            val[m] = g ? val[2 * m + 1] : val[2 * m];
            id[m]  = g ? id[2 * m + 1]  : id[2 * m];
        }
        if constexpr (W & 1) { val[P] = val[W - 1]; id[P] = id[W - 1]; }
        argmax_tree<((W + 1) >> 1)>(val, id);
    }
}

// ---------------------------------------------------------------------------
// Kernel 2: fused Viterbi forward + backtrace. One CTA (224 thr) per batch.
// Thread (j, r): j = tid>>2 in [0,56) (padded), r = tid&3, slice = 16 states
// at i0 = r*16 (pads -inf). vr read as 4x LDS.128. Epilogue distributed:
// r==2 owns feats ring + v-store, r==1 stores bp. No j<50 predicates in the
// hot loop: -inf transition pads keep pad lanes inert (v pads stay -inf).
// ---------------------------------------------------------------------------
__global__ __launch_bounds__(224, 1) void viterbi_kernel(
    const float* __restrict__ trans, const float* __restrict__ startt,
    const float* __restrict__ stopt, float* __restrict__ out) {
    extern __shared__ char smv[];
    unsigned char* bp = reinterpret_cast<unsigned char*>(smv);        // 1023*56 -> 57344 pad
    float* vbuf = reinterpret_cast<float*>(smv + 57344);              // [2][64]
    float* red  = vbuf + 128;                                         // [64]
    unsigned char* tags = reinterpret_cast<unsigned char*>(red + 64); // [1024]

    const int b = blockIdx.x;
    const int tid = threadIdx.x;
    const int j = tid >> 2;       // 0..55
    const int r = tid & 3;
    const float* F = g_feats + (size_t)b * GT * GK;
    const int i0 = r * 16;

    // Transition slice trans[i][j], i in [i0, i0+16); -inf pads (i>=50 or j>=50)
    float tr[16];
#pragma unroll
    for (int ii = 0; ii < 16; ii++) {
        int i = i0 + ii;
        tr[ii] = (j < GK && i < GK) ? trans[i * GK + j] : -INFINITY;
    }

    // Init: pad slots [50,64) of both halves to -inf; t=0 values for j<50
    if (r == 0) {
        float v0 = (j < GK) ? (F[j] + startt[j]) : -INFINITY;
        vbuf[j] = v0;
        vbuf[64 + j] = -INFINITY;
    }
    if (tid >= JP && tid < JP + 8) {          // slots 56..63, both halves
        vbuf[tid] = -INFINITY;
        vbuf[64 + tid] = -INFINITY;
    }

    // Feats prefetch ring (owned by r==2), depth 4
    float fr[4];
    if (r == 2) {
#pragma unroll
        for (int u = 0; u < 4; u++) fr[u] = F[(1 + u) * GK + j];
    }
    __syncthreads();

    for (int t = 1; t < GT; t += 4) {
#pragma unroll
        for (int u = 0; u < 4; u++) {
            const int tt = t + u;
            if (tt < GT) {  // uniform across block: barrier inside is legal
                const float4* vr = reinterpret_cast<const float4*>(
                    vbuf + (((tt - 1) & 1) << 6) + i0);
                float cand[16];
                int id[16];
#pragma unroll
                for (int q = 0; q < 4; q++) {
                    float4 x = vr[q];
                    cand[4 * q]     = x.x + tr[4 * q];
                    cand[4 * q + 1] = x.y + tr[4 * q + 1];
                    cand[4 * q + 2] = x.z + tr[4 * q + 2];
                    cand[4 * q + 3] = x.w + tr[4 * q + 3];
                }
#pragma unroll
                for (int ii = 0; ii < 16; ii++) id[ii] = i0 + ii;
                argmax_tree<16>(cand, id);
                float best = cand[0];
                int bi = id[0];

                // Merge 4 partials across r (lower index wins ties)
                float ov = __shfl_xor_sync(0xffffffffu, best, 1);
                int   oi = __shfl_xor_sync(0xffffffffu, bi, 1);
                bool g1 = (ov > best) || (ov == best && oi < bi);
                best = g1 ? ov : best;
                bi   = g1 ? oi : bi;
                ov = __shfl_xor_sync(0xffffffffu, best, 2);
                oi = __shfl_xor_sync(0xffffffffu, bi, 2);
                bool g2 = (ov > best) || (ov == best && oi < bi);
                best = g2 ? ov : best;
                bi   = g2 ? oi : bi;

                if (r == 2) {
                    // v-store: for j>=50, best=-inf so pad stays -inf
                    vbuf[((tt & 1) << 6) + j] = fr[u] + best;
                    int tn = tt + 4;
                    if (tn > GT - 1) tn = GT - 1;
                    fr[u] = F[tn * GK + j];
                } else if (r == 1) {
                    bp[(tt - 1) * BPP + j] = (unsigned char)bi;
                }
                __syncthreads();
            }
        }
    }

    // Final: v at t=1023 lives in buffer half 1
    if (r == 0 && j < GK) red[j] = vbuf[64 + j] + stopt[j];
    __syncthreads();

    if (tid == 0) {
        float best = -INFINITY;
        int bj = 0;
        for (int k = 0; k < GK; k++) {
            float s = red[k];
            if (s > best) { best = s; bj = k; }
        }
        out[b] = best;
        int tag = bj;
        tags[GT - 1] = (unsigned char)tag;
        for (int k = GT - 2; k >= 0; k--) {
            tag = bp[k * BPP + tag];
            tags[k] = (unsigned char)tag;
        }
    }
    __syncthreads();

    // Parallel coalesced tag writeout
    float* tout = out + GB + (size_t)b * GT;
    for (int k = tid; k < GT; k += 224) tout[k] = (float)tags[k];
}

extern "C" void kernel_launch(void* const* d_in, const int* in_sizes, int n_in,
                              void* d_out, int out_size) {
    const float* hidden = (const float*)d_in[0];
    const float* W      = (const float*)d_in[1];
    const float* bias   = (const float*)d_in[2];
    const float* trans  = (const float*)d_in[3];
    const float* startt = (const float*)d_in[4];
    const float* stopt  = (const float*)d_in[5];
    float* out = (float*)d_out;

    const size_t wsm = (size_t)GH * KPAD * sizeof(float);          // 106,496 B
    cudaFuncSetAttribute(gemm_kernel, cudaFuncAttributeMaxDynamicSharedMemorySize, (int)wsm);
    gemm_kernel<<<GM / 512, 256, wsm>>>(hidden, W, bias);

    const size_t vsm = 57344 + (128 + 64) * sizeof(float) + 1024;  // 59,136 B
    cudaFuncSetAttribute(viterbi_kernel, cudaFuncAttributeMaxDynamicSharedMemorySize, (int)vsm);
    viterbi_kernel<<<GB, 224, vsm>>>(trans, startt, stopt, out);
}